// round 6
// baseline (speedup 1.0000x reference)
#include <cuda_runtime.h>
#include <math.h>

// Problem constants
#define T_STEPS 300
#define BATCH   64
#define NH      512
#define D_IN    10
#define D_OUT   2

#define OUTS_SZ (T_STEPS*BATCH*D_OUT)
#define RSZ     (T_STEPS*BATCH*NH)
#define BN      (BATCH*NH)
#define NBLK    128

typedef unsigned long long u64;

// Persistent device scratch (no allocation — __device__ globals)
__device__ float g_rA[2][3][NH][BATCH];     // rates, k-major, double-buffered
__device__ unsigned g_cnt = 0;              // barrier arrival counter
__device__ volatile unsigned g_gen = 0;     // barrier generation

// ---- f32x2 packed math (sm_103a) -----------------------------------------
__device__ __forceinline__ u64 pk2(float x, float y) {
    u64 r; asm("mov.b64 %0,{%1,%2};" : "=l"(r) : "f"(x), "f"(y)); return r;
}
__device__ __forceinline__ float2 upk2(u64 v) {
    float2 r; asm("mov.b64 {%0,%1},%2;" : "=f"(r.x), "=f"(r.y) : "l"(v)); return r;
}
__device__ __forceinline__ void fma2(u64 &d, u64 a, u64 b) {
    asm("fma.rn.f32x2 %0,%1,%2,%0;" : "+l"(d) : "l"(a), "l"(b));
}
__device__ __forceinline__ u64 add2(u64 a, u64 b) {
    u64 d; asm("add.rn.f32x2 %0,%1,%2;" : "=l"(d) : "l"(a), "l"(b)); return d;
}

// ---- dynamic shared memory layout -----------------------------------------
struct Smem {
    float Ws[3*NH][8];            // resident weights: 48 KB
    float Red[2][8][64][9];       // K-reduction scratch x2 banks: 36 KB (scalar access)
    float stim_s[BATCH][D_IN];    // current stimulus: 2.5 KB
    float Win[D_IN][8];           // W_in_s1 columns: 320 B
};

// ---- grid barrier (all 128 blocks resident; 1 block/SM) -------------------
__device__ __forceinline__ void grid_bar(unsigned* mygen) {
    __threadfence();                       // publish this thread's stores
    __syncthreads();
    if (threadIdx.x == 0) {
        unsigned g = *mygen;
        unsigned old = atomicAdd(&g_cnt, 1);
        if (old == NBLK-1) { g_cnt = 0; __threadfence(); g_gen = g + 1; }
        else { while (g_gen == g) __nanosleep(32); }
    }
    __syncthreads();
    (*mygen)++;
}

// ---- one 64-k panel of FFMA2 ----------------------------------------------
__device__ __forceinline__ void panel_fma(
    const float4* __restrict__ cur, const float (* __restrict__ Ws)[8],
    int wrow, int kh, u64 acc[4][4])
{
    #pragma unroll
    for (int i = 0; i < 4; i++) {
        int wr = wrow + kh*4 + i;
        ulonglong2 wA = *(const ulonglong2*)&Ws[wr][0];
        ulonglong2 wB = *(const ulonglong2*)&Ws[wr][4];
        float4 av = cur[i];
        u64 a0 = pk2(av.x, av.x);
        u64 a1 = pk2(av.y, av.y);
        u64 a2 = pk2(av.z, av.z);
        u64 a3 = pk2(av.w, av.w);
        fma2(acc[0][0],a0,wA.x); fma2(acc[0][1],a0,wA.y);
        fma2(acc[0][2],a0,wB.x); fma2(acc[0][3],a0,wB.y);
        fma2(acc[1][0],a1,wA.x); fma2(acc[1][1],a1,wA.y);
        fma2(acc[1][2],a1,wB.x); fma2(acc[1][3],a1,wB.y);
        fma2(acc[2][0],a2,wA.x); fma2(acc[2][1],a2,wA.y);
        fma2(acc[2][2],a2,wB.x); fma2(acc[2][3],a2,wB.y);
        fma2(acc[3][0],a3,wA.x); fma2(acc[3][1],a3,wA.y);
        fma2(acc[3][2],a3,wB.x); fma2(acc[3][3],a3,wB.y);
    }
}

__device__ __forceinline__ void panel_ld(
    const float* const* __restrict__ S, int p, int kh, int rg, float4* dst)
{
    const float* A = S[p>>3];
    int k0 = (p&7) << 6;
    #pragma unroll
    for (int i = 0; i < 4; i++)
        dst[i] = __ldcg((const float4*)&A[(k0 + kh*4 + i)*BATCH + rg*4]);
}

// ---- shfl-fold 16 k-slices -> 8, park partials in a Red bank --------------
__device__ __forceinline__ void reduce_to_red(
    u64 acc[4][4], float (* __restrict__ Red)[64][9], int tid)
{
    const int w = tid >> 5, rg = tid & 15;
    #pragma unroll
    for (int r = 0; r < 4; r++)
        #pragma unroll
        for (int c = 0; c < 4; c++)
            acc[r][c] = add2(acc[r][c], __shfl_xor_sync(0xffffffffu, acc[r][c], 16));
    if ((tid & 16) == 0) {
        #pragma unroll
        for (int r = 0; r < 4; r++)
            #pragma unroll
            for (int c = 0; c < 4; c++) {
                float2 v = upk2(acc[r][c]);
                // scalar stores: rows are 9 floats (36B) — float2 would misalign
                Red[w][rg*4 + r][2*c]   = v.x;
                Red[w][rg*4 + r][2*c+1] = v.y;
            }
    }
}

// ---- final: sum 8 partials, leaky update, tanh, write rates ---------------
__device__ __forceinline__ void finish_region(
    int reg, const float (* __restrict__ Red)[64][9], float biasv,
    bool add_stim, Smem& sm, int t, int pw, int jj, float& x0, float& x1,
    float* __restrict__ d_out)
{
    const int tid = threadIdx.x;
    const int j = tid & 7;
    float* rates = d_out + OUTS_SZ + (size_t)reg*RSZ + (size_t)t*BN;
    float* gw = &g_rA[pw][reg][jj][0];
    #pragma unroll
    for (int h = 0; h < 2; h++) {
        int b = (tid >> 3) + h*32;
        float s = 0.f;
        #pragma unroll
        for (int q = 0; q < 8; q++) s += Red[q][b][j];
        float v = s + biasv;
        if (add_stim) {
            #pragma unroll
            for (int k = 0; k < D_IN; k++)
                v = fmaf(sm.stim_s[b][k], sm.Win[k][j], v);
        }
        float& x = h ? x1 : x0;
        x = 0.8f*x + 0.2f*v;
        float rr = tanhf(x);
        rates[b*NH + jj] = rr;        // [T,B,N] output layout
        __stcg(&gw[b], rr);           // k-major for next step (L2 coherent)
    }
}

// ---------------------------------------------------------------------------
// Persistent RNN: weights in smem, X state in registers, 1 grid barrier/step.
//   blocks [0,64)   : pmd cols 8*bid — 24 panels into accA
//   blocks [64,128) : m1 (16 panels -> accA) + s1 (8 panels -> accB), one
//                     fused 24-panel stream + single merged epilogue.
// Panel pipeline: ring of 4 register buffers, prefetch distance 2.
// ---------------------------------------------------------------------------
__global__ void __launch_bounds__(256,1) rnn_persistent(
    const float* __restrict__ W_rec_m1, const float* __restrict__ W_rec_pmd,
    const float* __restrict__ W_rec_s1, const float* __restrict__ W_pmd_m1,
    const float* __restrict__ b_pmd_m1, const float* __restrict__ W_m1_pmd,
    const float* __restrict__ b_m1_pmd, const float* __restrict__ W_s1_pmd,
    const float* __restrict__ b_s1_pmd, const float* __restrict__ W_in_s1,
    const float* __restrict__ b_in_s1, const float* __restrict__ W_out,
    const float* __restrict__ b_out,   const float* __restrict__ W_fb,
    const float* __restrict__ b_fb,    const float* __restrict__ stim,
    float* __restrict__ d_out)
{
    extern __shared__ char sraw[];
    Smem& sm = *reinterpret_cast<Smem*>(sraw);

    const int tid = threadIdx.x, bid = blockIdx.x;
    const bool pmdB = bid < 64;
    const int jb = (pmdB ? bid : bid - 64) << 3;
    const int jj = jb + (tid & 7);

    // ---- load weights into smem (once) ----
    if (pmdB) {
        for (int r = tid; r < NH; r += 256) {
            float wo0 = W_out[r*2], wo1 = W_out[r*2+1];
            #pragma unroll
            for (int q = 0; q < 8; q++) {
                int col = jb + q;
                sm.Ws[r][q]        = W_rec_pmd[r*NH + col];
                sm.Ws[NH + r][q]   = W_m1_pmd[r*NH + col]
                                   + wo0*W_fb[col] + wo1*W_fb[NH + col];
                sm.Ws[2*NH + r][q] = W_s1_pmd[r*NH + col];
            }
        }
    } else {
        for (int r = tid; r < NH; r += 256) {
            #pragma unroll
            for (int q = 0; q < 8; q++) {
                int col = jb + q;
                sm.Ws[r][q]        = W_rec_m1[r*NH + col];
                sm.Ws[NH + r][q]   = W_pmd_m1[r*NH + col];
                sm.Ws[2*NH + r][q] = W_rec_s1[r*NH + col];
            }
        }
        for (int i = tid; i < D_IN*8; i += 256)
            sm.Win[i>>3][i&7] = W_in_s1[(i>>3)*NH + jb + (i&7)];
    }

    // ---- fold biases into registers ----
    float bias0, bias_ex = 0.f, bias_s1 = 0.f;
    if (pmdB) {
        bias0   = b_m1_pmd[jj] + b_s1_pmd[jj] + b_fb[jj];
        bias_ex = b_out[0]*W_fb[jj] + b_out[1]*W_fb[NH + jj];
    } else {
        bias0   = b_pmd_m1[jj];
        bias_s1 = b_in_s1[jj];
    }

    // ---- zero parity-0 rates and t=0 output slices ----
    {
        float* rA0 = &g_rA[0][0][0][0];
        for (int i = bid*256 + tid; i < 3*NH*BATCH; i += NBLK*256)
            __stcg(&rA0[i], 0.f);
        float* r0 = d_out + OUTS_SZ;
        for (int i = bid*256 + tid; i < BN; i += NBLK*256) {
            r0[i] = 0.f; r0[RSZ + i] = 0.f; r0[2*RSZ + i] = 0.f;
        }
        if (bid == 0 && tid < BATCH*D_OUT) d_out[tid] = 0.f;
    }

    float x_a0 = 0.f, x_a1 = 0.f;   // pmd (pmd-block) / m1 (m1s1-block)
    float x_b0 = 0.f, x_b1 = 0.f;   // s1 (m1s1-block)

    unsigned mygen = g_gen;
    grid_bar(&mygen);

    const int kh = tid >> 4, rg = tid & 15;
    u64 accA[4][4], accB[4][4];
    float4 ring[4][4];
    const float* S[3];

    for (int t = 1; t < T_STEPS; t++) {
        const int pr = (t-1) & 1, pw = t & 1;
        const float* Am1  = &g_rA[pr][0][0][0];
        const float* Apmd = &g_rA[pr][1][0][0];
        const float* As1  = &g_rA[pr][2][0][0];

        #pragma unroll
        for (int r = 0; r < 4; r++)
            #pragma unroll
            for (int c = 0; c < 4; c++) { accA[r][c] = 0ull; accB[r][c] = 0ull; }

        if (pmdB) {
            S[0] = Apmd; S[1] = Am1; S[2] = As1;
            panel_ld(S, 0, kh, rg, ring[0]);
            panel_ld(S, 1, kh, rg, ring[1]);
            #pragma unroll 4
            for (int p = 0; p < 24; p++) {
                if (p + 2 < 24) panel_ld(S, p + 2, kh, rg, ring[(p+2)&3]);
                panel_fma(ring[p&3], sm.Ws, p*64, kh, accA);
            }
            reduce_to_red(accA, sm.Red[0], tid);
            __syncthreads();
            float bv = (t == 1) ? bias0 : (bias0 + bias_ex);
            finish_region(1, sm.Red[0], bv, false, sm, t, pw, jj, x_a0, x_a1, d_out);
        } else {
            // stage current stimulus for the s1 term (used after the Red sync)
            if (tid < 160)
                ((float4*)&sm.stim_s[0][0])[tid] =
                    __ldg((const float4*)(stim + (size_t)t*BATCH*D_IN) + tid);
            S[0] = Am1; S[1] = Apmd; S[2] = As1;
            panel_ld(S, 0, kh, rg, ring[0]);
            panel_ld(S, 1, kh, rg, ring[1]);
            #pragma unroll 4
            for (int p = 0; p < 16; p++) {          // m1: 2 sources -> accA
                panel_ld(S, p + 2, kh, rg, ring[(p+2)&3]);
                panel_fma(ring[p&3], sm.Ws, p*64, kh, accA);
            }
            #pragma unroll 4
            for (int p = 16; p < 24; p++) {         // s1: 1 source -> accB
                if (p + 2 < 24) panel_ld(S, p + 2, kh, rg, ring[(p+2)&3]);
                panel_fma(ring[p&3], sm.Ws, p*64, kh, accB);
            }
            reduce_to_red(accA, sm.Red[0], tid);
            reduce_to_red(accB, sm.Red[1], tid);
            __syncthreads();
            finish_region(0, sm.Red[0], bias0,  false, sm, t, pw, jj, x_a0, x_a1, d_out);
            finish_region(2, sm.Red[1], bias_s1, true, sm, t, pw, jj, x_b0, x_b1, d_out);
        }
        grid_bar(&mygen);   // its __syncthreads also protects Red/stim reuse
    }
}

// ---------------------------------------------------------------------------
// Readout: outs[t] = r_m1[t] @ W_out + b_out (t>=1); zeros at t=0.
// ---------------------------------------------------------------------------
__global__ void finale_kernel(const float* __restrict__ W_out,
                              const float* __restrict__ b_out,
                              float* __restrict__ d_out)
{
    const int t = blockIdx.x;
    const int u = threadIdx.x;       // 0..127
    const int b = u >> 1, d = u & 1;

    if (t == 0) { d_out[u] = 0.0f; return; }

    const float* rm = d_out + OUTS_SZ + (size_t)t*BN + b*NH;
    float a0=0.f, a1=0.f, a2=0.f, a3=0.f;
    for (int k = 0; k < NH; k += 4) {
        float4 r4 = *reinterpret_cast<const float4*>(&rm[k]);
        a0 = fmaf(r4.x, W_out[(k+0)*2 + d], a0);
        a1 = fmaf(r4.y, W_out[(k+1)*2 + d], a1);
        a2 = fmaf(r4.z, W_out[(k+2)*2 + d], a2);
        a3 = fmaf(r4.w, W_out[(k+3)*2 + d], a3);
    }
    d_out[t*BATCH*D_OUT + b*D_OUT + d] = b_out[d] + (a0 + a1) + (a2 + a3);
}

// ---------------------------------------------------------------------------
extern "C" void kernel_launch(void* const* d_in, const int* in_sizes, int n_in,
                              void* d_out, int out_size)
{
    const float* stim      = (const float*)d_in[0];
    const float* W_rec_m1  = (const float*)d_in[1];
    const float* W_rec_pmd = (const float*)d_in[2];
    const float* W_rec_s1  = (const float*)d_in[3];
    const float* W_pmd_m1  = (const float*)d_in[4];
    const float* b_pmd_m1  = (const float*)d_in[5];
    const float* W_m1_pmd  = (const float*)d_in[6];
    const float* b_m1_pmd  = (const float*)d_in[7];
    const float* W_s1_pmd  = (const float*)d_in[8];
    const float* b_s1_pmd  = (const float*)d_in[9];
    const float* W_in_s1   = (const float*)d_in[10];
    const float* b_in_s1   = (const float*)d_in[11];
    const float* W_out_m1  = (const float*)d_in[12];
    const float* b_out_m1  = (const float*)d_in[13];
    const float* W_fb_pmd  = (const float*)d_in[14];
    const float* b_fb_pmd  = (const float*)d_in[15];
    float* out = (float*)d_out;

    // Idempotent, capture-safe; no static guard.
    cudaFuncSetAttribute(rnn_persistent,
                         cudaFuncAttributeMaxDynamicSharedMemorySize,
                         (int)sizeof(Smem));

    rnn_persistent<<<NBLK, 256, sizeof(Smem)>>>(
        W_rec_m1, W_rec_pmd, W_rec_s1, W_pmd_m1, b_pmd_m1, W_m1_pmd,
        b_m1_pmd, W_s1_pmd, b_s1_pmd, W_in_s1, b_in_s1,
        W_out_m1, b_out_m1, W_fb_pmd, b_fb_pmd, stim, out);

    finale_kernel<<<T_STEPS, 128>>>(W_out_m1, b_out_m1, out);
}

// round 7
// speedup vs baseline: 1.4266x; 1.4266x over previous
#include <cuda_runtime.h>
#include <math.h>

// Problem constants
#define T_STEPS 300
#define BATCH   64
#define NH      512
#define D_IN    10
#define D_OUT   2

#define OUTS_SZ (T_STEPS*BATCH*D_OUT)
#define RSZ     (T_STEPS*BATCH*NH)
#define BN      (BATCH*NH)
#define NBLK    128
#define WPAD    20                           // Ws row pad: 80B (16B-aligned, conflict-free)

typedef unsigned long long u64;

// Persistent device scratch (no allocation — __device__ globals)
__device__ float g_rA[2][3][NH][BATCH];     // rates, k-major, double-buffered
__device__ unsigned g_cnt = 0;              // barrier arrival counter
__device__ volatile unsigned g_gen = 0;     // barrier generation

// ---- f32x2 packed math (sm_103a) -----------------------------------------
__device__ __forceinline__ u64 pk2(float x, float y) {
    u64 r; asm("mov.b64 %0,{%1,%2};" : "=l"(r) : "f"(x), "f"(y)); return r;
}
__device__ __forceinline__ float2 upk2(u64 v) {
    float2 r; asm("mov.b64 {%0,%1},%2;" : "=f"(r.x), "=f"(r.y) : "l"(v)); return r;
}
__device__ __forceinline__ void fma2(u64 &d, u64 a, u64 b) {
    asm("fma.rn.f32x2 %0,%1,%2,%0;" : "+l"(d) : "l"(a), "l"(b));
}
__device__ __forceinline__ u64 add2(u64 a, u64 b) {
    u64 d; asm("add.rn.f32x2 %0,%1,%2;" : "=l"(d) : "l"(a), "l"(b)); return d;
}

// ---- dynamic shared memory layout -----------------------------------------
// Block owns 16 output cols x 32-batch half. Ws: 3 sources x 512 k x 16 cols.
struct Smem {
    float Ws[3*NH][WPAD];         // resident weights: 120 KB (16 used + 4 pad)
    float RedA[8][32][17];        // K-reduction bank A: 17 KB (scalar access)
    float RedB[8][32][17];        // K-reduction bank B: 17 KB
    float stim_s[BATCH][D_IN];    // current stimulus: 2.5 KB
    float Win[D_IN][16];          // W_in_s1 columns: 640 B
};

// ---- grid barrier (all 128 blocks resident; 1 block/SM) -------------------
__device__ __forceinline__ void grid_bar(unsigned* mygen) {
    __threadfence();                       // publish this thread's stores
    __syncthreads();
    if (threadIdx.x == 0) {
        unsigned g = *mygen;
        unsigned old = atomicAdd(&g_cnt, 1);
        if (old == NBLK-1) { g_cnt = 0; __threadfence(); g_gen = g + 1; }
        else { while (g_gen == g) __nanosleep(32); }
    }
    __syncthreads();
    (*mygen)++;
}

// ---- GEMM accumulate: NSEG sources of 8 panels (64 k x 32 batch) ----------
// Thread (kh=tid>>4, ch=(tid>>3)&1, bg=tid&7): 4 k x 4 batch x 8 cols/panel.
// A from L2 (__ldcg, coalesced), W broadcast from smem (WPAD rows: aligned,
// conflict-free). Explicit cur/nxt double buffer — NO indexed register arrays
// (R5 lesson: ring[] indexing demotes to local memory).
template<int NSEG>
__device__ __forceinline__ void compute_accum(
    const float* __restrict__ A0, const float* __restrict__ A1,
    const float* __restrict__ A2, int wbase,
    const float (* __restrict__ Ws)[WPAD], int kh, int ch, int bg, int bo,
    u64 acc[4][4])
{
    #pragma unroll
    for (int r = 0; r < 4; r++)
        #pragma unroll
        for (int c = 0; c < 4; c++) acc[r][c] = 0ull;

    const int np = NSEG*8;
    float4 cur[4], nxt[4];

    #pragma unroll
    for (int i = 0; i < 4; i++)
        cur[i] = __ldcg((const float4*)&A0[(kh*4 + i)*BATCH + bo + bg*4]);

    for (int p = 0; p < np; p++) {
        if (p + 1 < np) {
            int s = (p+1) >> 3;
            const float* Ap = (s == 0) ? A0 : (s == 1) ? A1 : A2;
            int k0 = ((p+1) & 7) << 6;
            #pragma unroll
            for (int i = 0; i < 4; i++)
                nxt[i] = __ldcg((const float4*)&Ap[(k0 + kh*4 + i)*BATCH + bo + bg*4]);
        }
        #pragma unroll
        for (int i = 0; i < 4; i++) {
            int wr = wbase + p*64 + kh*4 + i;
            ulonglong2 wA = *(const ulonglong2*)&Ws[wr][ch*8];
            ulonglong2 wB = *(const ulonglong2*)&Ws[wr][ch*8 + 4];
            float4 av = cur[i];
            u64 a0 = pk2(av.x, av.x);
            u64 a1 = pk2(av.y, av.y);
            u64 a2 = pk2(av.z, av.z);
            u64 a3 = pk2(av.w, av.w);
            fma2(acc[0][0],a0,wA.x); fma2(acc[0][1],a0,wA.y);
            fma2(acc[0][2],a0,wB.x); fma2(acc[0][3],a0,wB.y);
            fma2(acc[1][0],a1,wA.x); fma2(acc[1][1],a1,wA.y);
            fma2(acc[1][2],a1,wB.x); fma2(acc[1][3],a1,wB.y);
            fma2(acc[2][0],a2,wA.x); fma2(acc[2][1],a2,wA.y);
            fma2(acc[2][2],a2,wB.x); fma2(acc[2][3],a2,wB.y);
            fma2(acc[3][0],a3,wA.x); fma2(acc[3][1],a3,wA.y);
            fma2(acc[3][2],a3,wB.x); fma2(acc[3][3],a3,wB.y);
        }
        #pragma unroll
        for (int i = 0; i < 4; i++) cur[i] = nxt[i];
    }
}

// ---- shfl-fold 16 k-slices -> 8, park partials in a Red bank --------------
__device__ __forceinline__ void reduce_to_red(
    u64 acc[4][4], float (* __restrict__ Red)[32][17], int tid)
{
    const int w = tid >> 5, ch = (tid >> 3) & 1, bg = tid & 7;
    #pragma unroll
    for (int r = 0; r < 4; r++)
        #pragma unroll
        for (int c = 0; c < 4; c++)
            acc[r][c] = add2(acc[r][c], __shfl_xor_sync(0xffffffffu, acc[r][c], 16));
    if ((tid & 16) == 0) {      // even-kh lanes hold the fold
        #pragma unroll
        for (int r = 0; r < 4; r++)
            #pragma unroll
            for (int c = 0; c < 4; c++) {
                float2 v = upk2(acc[r][c]);
                // scalar stores (17-float rows would misalign float2)
                Red[w][bg*4 + r][ch*8 + 2*c]   = v.x;
                Red[w][bg*4 + r][ch*8 + 2*c+1] = v.y;
            }
    }
}

// ---- final: sum 8 partials, leaky update, tanh, write rates ---------------
__device__ __forceinline__ void finish_region(
    int reg, const float (* __restrict__ Red)[32][17], float biasv,
    bool add_stim, Smem& sm, int t, int pw, int jb, int bo,
    float& x0, float& x1, float* __restrict__ d_out)
{
    const int tid = threadIdx.x;
    const int j = tid & 15, jj = jb + j;
    float* rates = d_out + OUTS_SZ + (size_t)reg*RSZ + (size_t)t*BN;
    float* gw = &g_rA[pw][reg][jj][0];
    #pragma unroll
    for (int h = 0; h < 2; h++) {
        int bloc = (tid >> 4) + h*16;      // 0..31 within the batch half
        int b = bo + bloc;
        float s = 0.f;
        #pragma unroll
        for (int q = 0; q < 8; q++) s += Red[q][bloc][j];
        float v = s + biasv;
        if (add_stim) {
            #pragma unroll
            for (int k = 0; k < D_IN; k++)
                v = fmaf(sm.stim_s[b][k], sm.Win[k][j], v);
        }
        float& x = h ? x1 : x0;
        x = 0.8f*x + 0.2f*v;
        float rr = tanhf(x);
        rates[b*NH + jj] = rr;        // [T,B,N] output layout
        __stcg(&gw[b], rr);           // k-major for next step (L2 coherent)
    }
}

// ---------------------------------------------------------------------------
// Persistent RNN: weights in smem, X state in registers, 1 grid barrier/step.
// Block = 16 output cols x 32-batch half (halves per-step L2 A-traffic vs 8-col
// blocks: 24.5 MB instead of 49 MB).
//   blocks [0,64)   : pmd — cg=bid>>1, bh=bid&1; 24 panels
//   blocks [64,128) : m1 (16 panels) + s1 (8 panels), Red banks A/B, 1 sync
// ---------------------------------------------------------------------------
__global__ void __launch_bounds__(256,1) rnn_persistent(
    const float* __restrict__ W_rec_m1, const float* __restrict__ W_rec_pmd,
    const float* __restrict__ W_rec_s1, const float* __restrict__ W_pmd_m1,
    const float* __restrict__ b_pmd_m1, const float* __restrict__ W_m1_pmd,
    const float* __restrict__ b_m1_pmd, const float* __restrict__ W_s1_pmd,
    const float* __restrict__ b_s1_pmd, const float* __restrict__ W_in_s1,
    const float* __restrict__ b_in_s1, const float* __restrict__ W_out,
    const float* __restrict__ b_out,   const float* __restrict__ W_fb,
    const float* __restrict__ b_fb,    const float* __restrict__ stim,
    float* __restrict__ d_out)
{
    extern __shared__ char sraw[];
    Smem& sm = *reinterpret_cast<Smem*>(sraw);

    const int tid = threadIdx.x, bid = blockIdx.x;
    const bool pmdB = bid < 64;
    const int lb = pmdB ? bid : bid - 64;
    const int jb = (lb >> 1) << 4;        // 16-col group
    const int bo = (lb & 1) << 5;         // batch half offset
    const int jj = jb + (tid & 15);

    // ---- load weights into smem (once) ----
    if (pmdB) {
        for (int r = tid; r < NH; r += 256) {
            float wo0 = W_out[r*2], wo1 = W_out[r*2+1];
            #pragma unroll
            for (int q = 0; q < 16; q++) {
                int col = jb + q;
                sm.Ws[r][q]        = W_rec_pmd[r*NH + col];
                sm.Ws[NH + r][q]   = W_m1_pmd[r*NH + col]
                                   + wo0*W_fb[col] + wo1*W_fb[NH + col];
                sm.Ws[2*NH + r][q] = W_s1_pmd[r*NH + col];
            }
        }
    } else {
        for (int r = tid; r < NH; r += 256) {
            #pragma unroll
            for (int q = 0; q < 16; q++) {
                int col = jb + q;
                sm.Ws[r][q]        = W_rec_m1[r*NH + col];
                sm.Ws[NH + r][q]   = W_pmd_m1[r*NH + col];
                sm.Ws[2*NH + r][q] = W_rec_s1[r*NH + col];
            }
        }
        for (int i = tid; i < D_IN*16; i += 256)
            sm.Win[i>>4][i&15] = W_in_s1[(i>>4)*NH + jb + (i&15)];
    }

    // ---- fold biases into registers ----
    float bias0, bias_ex = 0.f, bias_s1 = 0.f;
    if (pmdB) {
        bias0   = b_m1_pmd[jj] + b_s1_pmd[jj] + b_fb[jj];
        bias_ex = b_out[0]*W_fb[jj] + b_out[1]*W_fb[NH + jj];
    } else {
        bias0   = b_pmd_m1[jj];
        bias_s1 = b_in_s1[jj];
    }

    // ---- zero parity-0 rates and t=0 output slices ----
    {
        float* rA0 = &g_rA[0][0][0][0];
        for (int i = bid*256 + tid; i < 3*NH*BATCH; i += NBLK*256)
            __stcg(&rA0[i], 0.f);
        float* r0 = d_out + OUTS_SZ;
        for (int i = bid*256 + tid; i < BN; i += NBLK*256) {
            r0[i] = 0.f; r0[RSZ + i] = 0.f; r0[2*RSZ + i] = 0.f;
        }
        if (bid == 0 && tid < BATCH*D_OUT) d_out[tid] = 0.f;
    }

    float x_a0 = 0.f, x_a1 = 0.f;   // pmd (pmd-block) / m1 (m1s1-block)
    float x_b0 = 0.f, x_b1 = 0.f;   // s1 (m1s1-block)

    unsigned mygen = g_gen;
    grid_bar(&mygen);

    const int kh = tid >> 4, ch = (tid >> 3) & 1, bg = tid & 7;
    u64 acc[4][4];

    for (int t = 1; t < T_STEPS; t++) {
        const int pr = (t-1) & 1, pw = t & 1;
        const float* Am1  = &g_rA[pr][0][0][0];
        const float* Apmd = &g_rA[pr][1][0][0];
        const float* As1  = &g_rA[pr][2][0][0];

        if (pmdB) {
            compute_accum<3>(Apmd, Am1, As1, 0, sm.Ws, kh, ch, bg, bo, acc);
            reduce_to_red(acc, sm.RedA, tid);
            __syncthreads();
            float bv = (t == 1) ? bias0 : (bias0 + bias_ex);
            finish_region(1, sm.RedA, bv, false, sm, t, pw, jb, bo, x_a0, x_a1, d_out);
        } else {
            // stage current stimulus (used after the Red sync)
            if (tid < 160)
                ((float4*)&sm.stim_s[0][0])[tid] =
                    __ldg((const float4*)(stim + (size_t)t*BATCH*D_IN) + tid);
            // m1: r_m1@W_rec_m1 + r_pmd@W_pmd_m1
            compute_accum<2>(Am1, Apmd, Apmd, 0, sm.Ws, kh, ch, bg, bo, acc);
            reduce_to_red(acc, sm.RedA, tid);
            // s1: r_s1@W_rec_s1 (acc reused — keeps register count at R4 level)
            compute_accum<1>(As1, As1, As1, 2*NH, sm.Ws, kh, ch, bg, bo, acc);
            reduce_to_red(acc, sm.RedB, tid);
            __syncthreads();
            finish_region(0, sm.RedA, bias0,  false, sm, t, pw, jb, bo, x_a0, x_a1, d_out);
            finish_region(2, sm.RedB, bias_s1, true, sm, t, pw, jb, bo, x_b0, x_b1, d_out);
        }
        grid_bar(&mygen);   // its syncthreads also protects Red/stim reuse
    }
}

// ---------------------------------------------------------------------------
// Readout: outs[t] = r_m1[t] @ W_out + b_out (t>=1); zeros at t=0.
// ---------------------------------------------------------------------------
__global__ void finale_kernel(const float* __restrict__ W_out,
                              const float* __restrict__ b_out,
                              float* __restrict__ d_out)
{
    const int t = blockIdx.x;
    const int u = threadIdx.x;       // 0..127
    const int b = u >> 1, d = u & 1;

    if (t == 0) { d_out[u] = 0.0f; return; }

    const float* rm = d_out + OUTS_SZ + (size_t)t*BN + b*NH;
    float a0=0.f, a1=0.f, a2=0.f, a3=0.f;
    for (int k = 0; k < NH; k += 4) {
        float4 r4 = *reinterpret_cast<const float4*>(&rm[k]);
        a0 = fmaf(r4.x, W_out[(k+0)*2 + d], a0);
        a1 = fmaf(r4.y, W_out[(k+1)*2 + d], a1);
        a2 = fmaf(r4.z, W_out[(k+2)*2 + d], a2);
        a3 = fmaf(r4.w, W_out[(k+3)*2 + d], a3);
    }
    d_out[t*BATCH*D_OUT + b*D_OUT + d] = b_out[d] + (a0 + a1) + (a2 + a3);
}

// ---------------------------------------------------------------------------
extern "C" void kernel_launch(void* const* d_in, const int* in_sizes, int n_in,
                              void* d_out, int out_size)
{
    const float* stim      = (const float*)d_in[0];
    const float* W_rec_m1  = (const float*)d_in[1];
    const float* W_rec_pmd = (const float*)d_in[2];
    const float* W_rec_s1  = (const float*)d_in[3];
    const float* W_pmd_m1  = (const float*)d_in[4];
    const float* b_pmd_m1  = (const float*)d_in[5];
    const float* W_m1_pmd  = (const float*)d_in[6];
    const float* b_m1_pmd  = (const float*)d_in[7];
    const float* W_s1_pmd  = (const float*)d_in[8];
    const float* b_s1_pmd  = (const float*)d_in[9];
    const float* W_in_s1   = (const float*)d_in[10];
    const float* b_in_s1   = (const float*)d_in[11];
    const float* W_out_m1  = (const float*)d_in[12];
    const float* b_out_m1  = (const float*)d_in[13];
    const float* W_fb_pmd  = (const float*)d_in[14];
    const float* b_fb_pmd  = (const float*)d_in[15];
    float* out = (float*)d_out;

    // Idempotent, capture-safe; no static guard.
    cudaFuncSetAttribute(rnn_persistent,
                         cudaFuncAttributeMaxDynamicSharedMemorySize,
                         (int)sizeof(Smem));

    rnn_persistent<<<NBLK, 256, sizeof(Smem)>>>(
        W_rec_m1, W_rec_pmd, W_rec_s1, W_pmd_m1, b_pmd_m1, W_m1_pmd,
        b_m1_pmd, W_s1_pmd, b_s1_pmd, W_in_s1, b_in_s1,
        W_out_m1, b_out_m1, W_fb_pmd, b_fb_pmd, stim, out);

    finale_kernel<<<T_STEPS, 128>>>(W_out_m1, b_out_m1, out);
}

// round 8
// speedup vs baseline: 1.6727x; 1.1725x over previous
#include <cuda_runtime.h>
#include <math.h>

// Problem constants
#define T_STEPS 300
#define BATCH   64
#define NH      512
#define D_IN    10
#define D_OUT   2

#define OUTS_SZ (T_STEPS*BATCH*D_OUT)
#define RSZ     (T_STEPS*BATCH*NH)
#define BN      (BATCH*NH)
#define NBLK    128

typedef unsigned long long u64;

// Persistent device scratch (no allocation — __device__ globals)
__device__ float g_rA[2][3][NH][BATCH];     // rates, k-major, double-buffered
__device__ unsigned g_cnt = 0;              // barrier arrival counter
__device__ unsigned g_gen = 0;              // barrier generation

// ---- f32x2 packed math (sm_103a) -----------------------------------------
__device__ __forceinline__ u64 pk2(float x, float y) {
    u64 r; asm("mov.b64 %0,{%1,%2};" : "=l"(r) : "f"(x), "f"(y)); return r;
}
__device__ __forceinline__ float2 upk2(u64 v) {
    float2 r; asm("mov.b64 {%0,%1},%2;" : "=f"(r.x), "=f"(r.y) : "l"(v)); return r;
}
__device__ __forceinline__ void fma2(u64 &d, u64 a, u64 b) {
    asm("fma.rn.f32x2 %0,%1,%2,%0;" : "+l"(d) : "l"(a), "l"(b));
}
__device__ __forceinline__ u64 add2(u64 a, u64 b) {
    u64 d; asm("add.rn.f32x2 %0,%1,%2;" : "=l"(d) : "l"(a), "l"(b)); return d;
}

// ---- acquire/release helpers for the grid barrier -------------------------
__device__ __forceinline__ unsigned ld_acq(unsigned* p) {
    unsigned v;
    asm volatile("ld.acquire.gpu.u32 %0,[%1];" : "=r"(v) : "l"(p) : "memory");
    return v;
}
__device__ __forceinline__ void st_rel(unsigned* p, unsigned v) {
    asm volatile("st.release.gpu.u32 [%0],%1;" :: "l"(p), "r"(v) : "memory");
}

// ---- dynamic shared memory layout -----------------------------------------
struct Smem {
    float Ws[3*NH][8];            // resident weights: 48 KB
    float RedA[8][64][9];         // K-reduction bank A: 18 KB (scalar access)
    float RedB[8][64][9];         // K-reduction bank B: 18 KB
    float stim_s[BATCH][D_IN];    // current stimulus: 2.5 KB
    float Win[D_IN][8];           // W_in_s1 columns: 320 B
};

// ---- grid barrier (all 128 blocks resident; 1 block/SM) -------------------
__device__ __forceinline__ void grid_bar(unsigned* mygen) {
    __threadfence();                       // publish this thread's stores
    __syncthreads();
    if (threadIdx.x == 0) {
        unsigned g = *mygen;
        unsigned old = atomicAdd(&g_cnt, 1);
        if (old == NBLK-1) { g_cnt = 0; st_rel(&g_gen, g + 1); }
        else { while (ld_acq(&g_gen) == g) { } }
    }
    __syncthreads();
    (*mygen)++;
}

// ---- panel primitives ------------------------------------------------------
// Thread (kh=tid>>4, rg=tid&15): 4 k-values x 4 batch x 8 cols per panel.
__device__ __forceinline__ void panel_ld(
    const float* const* __restrict__ S, int p, int kh, int rg, float4* dst)
{
    const float* A = S[p>>3];
    int k0 = (p&7) << 6;
    #pragma unroll
    for (int i = 0; i < 4; i++)
        dst[i] = __ldcg((const float4*)&A[(k0 + kh*4 + i)*BATCH + rg*4]);
}

__device__ __forceinline__ void panel_fma(
    const float4* __restrict__ cur, const float (* __restrict__ Ws)[8],
    int wrow, int kh, u64 acc[4][4])
{
    #pragma unroll
    for (int i = 0; i < 4; i++) {
        int wr = wrow + kh*4 + i;
        ulonglong2 wA = *(const ulonglong2*)&Ws[wr][0];   // full-warp broadcast
        ulonglong2 wB = *(const ulonglong2*)&Ws[wr][4];
        float4 av = cur[i];
        u64 a0 = pk2(av.x, av.x);
        u64 a1 = pk2(av.y, av.y);
        u64 a2 = pk2(av.z, av.z);
        u64 a3 = pk2(av.w, av.w);
        fma2(acc[0][0],a0,wA.x); fma2(acc[0][1],a0,wA.y);
        fma2(acc[0][2],a0,wB.x); fma2(acc[0][3],a0,wB.y);
        fma2(acc[1][0],a1,wA.x); fma2(acc[1][1],a1,wA.y);
        fma2(acc[1][2],a1,wB.x); fma2(acc[1][3],a1,wB.y);
        fma2(acc[2][0],a2,wA.x); fma2(acc[2][1],a2,wA.y);
        fma2(acc[2][2],a2,wB.x); fma2(acc[2][3],a2,wB.y);
        fma2(acc[3][0],a3,wA.x); fma2(acc[3][1],a3,wA.y);
        fma2(acc[3][2],a3,wB.x); fma2(acc[3][3],a3,wB.y);
    }
}

// ---- GEMM accumulate: NSEG sources of 8 panels, depth-3 prefetch ----------
// Four EXPLICIT named buffers, p-loop step 4 (NP in {8,16,24} all /4).
// No indexed register arrays (R5 lesson: they demote to local memory).
// Load->use distance = 3 panel computes (~768 cyc) -> covers L2 latency.
template<int NSEG>
__device__ __forceinline__ void compute_accum(
    const float* const* __restrict__ S, int wbase,
    const float (* __restrict__ Ws)[8], int kh, int rg, u64 acc[4][4])
{
    constexpr int NP = NSEG*8;
    #pragma unroll
    for (int r = 0; r < 4; r++)
        #pragma unroll
        for (int c = 0; c < 4; c++) acc[r][c] = 0ull;

    float4 bA[4], bB[4], bC[4], bD[4];
    panel_ld(S, 0, kh, rg, bA);
    panel_ld(S, 1, kh, rg, bB);
    panel_ld(S, 2, kh, rg, bC);

    for (int p = 0; p < NP; p += 4) {
        if (p + 3 < NP) panel_ld(S, p + 3, kh, rg, bD);
        panel_fma(bA, Ws, (wbase + p)*64, kh, acc);
        if (p + 4 < NP) panel_ld(S, p + 4, kh, rg, bA);
        panel_fma(bB, Ws, (wbase + p + 1)*64, kh, acc);
        if (p + 5 < NP) panel_ld(S, p + 5, kh, rg, bB);
        panel_fma(bC, Ws, (wbase + p + 2)*64, kh, acc);
        if (p + 6 < NP) panel_ld(S, p + 6, kh, rg, bC);
        panel_fma(bD, Ws, (wbase + p + 3)*64, kh, acc);
    }
}

// ---- shfl-fold 16 k-slices -> 8, park partials in a Red bank --------------
__device__ __forceinline__ void reduce_to_red(
    u64 acc[4][4], float (* __restrict__ Red)[64][9], int tid)
{
    const int w = tid >> 5, rg = tid & 15;
    #pragma unroll
    for (int r = 0; r < 4; r++)
        #pragma unroll
        for (int c = 0; c < 4; c++)
            acc[r][c] = add2(acc[r][c], __shfl_xor_sync(0xffffffffu, acc[r][c], 16));
    if ((tid & 16) == 0) {
        #pragma unroll
        for (int r = 0; r < 4; r++)
            #pragma unroll
            for (int c = 0; c < 4; c++) {
                float2 v = upk2(acc[r][c]);
                // scalar stores (9-float rows would misalign float2)
                Red[w][rg*4 + r][2*c]   = v.x;
                Red[w][rg*4 + r][2*c+1] = v.y;
            }
    }
}

// ---- final: sum 8 partials, leaky update, tanh, write rates ---------------
__device__ __forceinline__ void finish_region(
    int reg, const float (* __restrict__ Red)[64][9], float biasv,
    bool add_stim, Smem& sm, int t, int pw, int jj, float& x0, float& x1,
    float* __restrict__ d_out)
{
    const int tid = threadIdx.x;
    const int j = tid & 7;
    float* rates = d_out + OUTS_SZ + (size_t)reg*RSZ + (size_t)t*BN;
    float* gw = &g_rA[pw][reg][jj][0];
    #pragma unroll
    for (int h = 0; h < 2; h++) {
        int b = (tid >> 3) + h*32;
        float s = 0.f;
        #pragma unroll
        for (int q = 0; q < 8; q++) s += Red[q][b][j];
        float v = s + biasv;
        if (add_stim) {
            #pragma unroll
            for (int k = 0; k < D_IN; k++)
                v = fmaf(sm.stim_s[b][k], sm.Win[k][j], v);
        }
        float& x = h ? x1 : x0;
        x = 0.8f*x + 0.2f*v;
        float rr = tanhf(x);
        rates[b*NH + jj] = rr;        // [T,B,N] output layout
        __stcg(&gw[b], rr);           // k-major for next step (L2 coherent)
    }
}

// ---------------------------------------------------------------------------
// Persistent RNN: weights in smem, X state in registers, 1 grid barrier/step.
//   blocks [0,64)   : pmd cols 8*bid — 24 panels
//   blocks [64,128) : m1 (16 panels -> RedA) + s1 (8 panels -> RedB), 1 sync
// ---------------------------------------------------------------------------
__global__ void __launch_bounds__(256,1) rnn_persistent(
    const float* __restrict__ W_rec_m1, const float* __restrict__ W_rec_pmd,
    const float* __restrict__ W_rec_s1, const float* __restrict__ W_pmd_m1,
    const float* __restrict__ b_pmd_m1, const float* __restrict__ W_m1_pmd,
    const float* __restrict__ b_m1_pmd, const float* __restrict__ W_s1_pmd,
    const float* __restrict__ b_s1_pmd, const float* __restrict__ W_in_s1,
    const float* __restrict__ b_in_s1, const float* __restrict__ W_out,
    const float* __restrict__ b_out,   const float* __restrict__ W_fb,
    const float* __restrict__ b_fb,    const float* __restrict__ stim,
    float* __restrict__ d_out)
{
    extern __shared__ char sraw[];
    Smem& sm = *reinterpret_cast<Smem*>(sraw);

    const int tid = threadIdx.x, bid = blockIdx.x;
    const bool pmdB = bid < 64;
    const int jb = (pmdB ? bid : bid - 64) << 3;
    const int jj = jb + (tid & 7);

    // ---- load weights into smem (once) ----
    if (pmdB) {
        for (int r = tid; r < NH; r += 256) {
            float wo0 = W_out[r*2], wo1 = W_out[r*2+1];
            #pragma unroll
            for (int q = 0; q < 8; q++) {
                int col = jb + q;
                sm.Ws[r][q]        = W_rec_pmd[r*NH + col];
                sm.Ws[NH + r][q]   = W_m1_pmd[r*NH + col]
                                   + wo0*W_fb[col] + wo1*W_fb[NH + col];
                sm.Ws[2*NH + r][q] = W_s1_pmd[r*NH + col];
            }
        }
    } else {
        for (int r = tid; r < NH; r += 256) {
            #pragma unroll
            for (int q = 0; q < 8; q++) {
                int col = jb + q;
                sm.Ws[r][q]        = W_rec_m1[r*NH + col];
                sm.Ws[NH + r][q]   = W_pmd_m1[r*NH + col];
                sm.Ws[2*NH + r][q] = W_rec_s1[r*NH + col];
            }
        }
        for (int i = tid; i < D_IN*8; i += 256)
            sm.Win[i>>3][i&7] = W_in_s1[(i>>3)*NH + jb + (i&7)];
    }

    // ---- fold biases into registers ----
    float bias0, bias_ex = 0.f, bias_s1 = 0.f;
    if (pmdB) {
        bias0   = b_m1_pmd[jj] + b_s1_pmd[jj] + b_fb[jj];
        bias_ex = b_out[0]*W_fb[jj] + b_out[1]*W_fb[NH + jj];
    } else {
        bias0   = b_pmd_m1[jj];
        bias_s1 = b_in_s1[jj];
    }

    // ---- zero parity-0 rates and t=0 output slices ----
    {
        float* rA0 = &g_rA[0][0][0][0];
        for (int i = bid*256 + tid; i < 3*NH*BATCH; i += NBLK*256)
            __stcg(&rA0[i], 0.f);
        float* r0 = d_out + OUTS_SZ;
        for (int i = bid*256 + tid; i < BN; i += NBLK*256) {
            r0[i] = 0.f; r0[RSZ + i] = 0.f; r0[2*RSZ + i] = 0.f;
        }
        if (bid == 0 && tid < BATCH*D_OUT) d_out[tid] = 0.f;
    }

    float x_a0 = 0.f, x_a1 = 0.f;   // pmd (pmd-block) / m1 (m1s1-block)
    float x_b0 = 0.f, x_b1 = 0.f;   // s1 (m1s1-block)

    unsigned mygen = g_gen;
    grid_bar(&mygen);

    const int kh = tid >> 4, rg = tid & 15;
    u64 acc[4][4];
    const float* S[3];

    for (int t = 1; t < T_STEPS; t++) {
        const int pr = (t-1) & 1, pw = t & 1;
        const float* Am1  = &g_rA[pr][0][0][0];
        const float* Apmd = &g_rA[pr][1][0][0];
        const float* As1  = &g_rA[pr][2][0][0];

        if (pmdB) {
            S[0] = Apmd; S[1] = Am1; S[2] = As1;
            compute_accum<3>(S, 0, sm.Ws, kh, rg, acc);
            reduce_to_red(acc, sm.RedA, tid);
            __syncthreads();
            float bv = (t == 1) ? bias0 : (bias0 + bias_ex);
            finish_region(1, sm.RedA, bv, false, sm, t, pw, jj, x_a0, x_a1, d_out);
        } else {
            // stage current stimulus (used after the Red sync)
            if (tid < 160)
                ((float4*)&sm.stim_s[0][0])[tid] =
                    __ldg((const float4*)(stim + (size_t)t*BATCH*D_IN) + tid);
            S[0] = Am1; S[1] = Apmd; S[2] = As1;
            compute_accum<2>(S, 0, sm.Ws, kh, rg, acc);
            reduce_to_red(acc, sm.RedA, tid);
            S[0] = As1;
            compute_accum<1>(S, 16, sm.Ws, kh, rg, acc);
            reduce_to_red(acc, sm.RedB, tid);
            __syncthreads();
            finish_region(0, sm.RedA, bias0,  false, sm, t, pw, jj, x_a0, x_a1, d_out);
            finish_region(2, sm.RedB, bias_s1, true, sm, t, pw, jj, x_b0, x_b1, d_out);
        }
        grid_bar(&mygen);   // its __syncthreads also protects Red/stim reuse
    }
}

// ---------------------------------------------------------------------------
// Readout: outs[t] = r_m1[t] @ W_out + b_out (t>=1); zeros at t=0.
// ---------------------------------------------------------------------------
__global__ void finale_kernel(const float* __restrict__ W_out,
                              const float* __restrict__ b_out,
                              float* __restrict__ d_out)
{
    const int t = blockIdx.x;
    const int u = threadIdx.x;       // 0..127
    const int b = u >> 1, d = u & 1;

    if (t == 0) { d_out[u] = 0.0f; return; }

    const float* rm = d_out + OUTS_SZ + (size_t)t*BN + b*NH;
    float a0=0.f, a1=0.f, a2=0.f, a3=0.f;
    for (int k = 0; k < NH; k += 4) {
        float4 r4 = *reinterpret_cast<const float4*>(&rm[k]);
        a0 = fmaf(r4.x, W_out[(k+0)*2 + d], a0);
        a1 = fmaf(r4.y, W_out[(k+1)*2 + d], a1);
        a2 = fmaf(r4.z, W_out[(k+2)*2 + d], a2);
        a3 = fmaf(r4.w, W_out[(k+3)*2 + d], a3);
    }
    d_out[t*BATCH*D_OUT + b*D_OUT + d] = b_out[d] + (a0 + a1) + (a2 + a3);
}

// ---------------------------------------------------------------------------
extern "C" void kernel_launch(void* const* d_in, const int* in_sizes, int n_in,
                              void* d_out, int out_size)
{
    const float* stim      = (const float*)d_in[0];
    const float* W_rec_m1  = (const float*)d_in[1];
    const float* W_rec_pmd = (const float*)d_in[2];
    const float* W_rec_s1  = (const float*)d_in[3];
    const float* W_pmd_m1  = (const float*)d_in[4];
    const float* b_pmd_m1  = (const float*)d_in[5];
    const float* W_m1_pmd  = (const float*)d_in[6];
    const float* b_m1_pmd  = (const float*)d_in[7];
    const float* W_s1_pmd  = (const float*)d_in[8];
    const float* b_s1_pmd  = (const float*)d_in[9];
    const float* W_in_s1   = (const float*)d_in[10];
    const float* b_in_s1   = (const float*)d_in[11];
    const float* W_out_m1  = (const float*)d_in[12];
    const float* b_out_m1  = (const float*)d_in[13];
    const float* W_fb_pmd  = (const float*)d_in[14];
    const float* b_fb_pmd  = (const float*)d_in[15];
    float* out = (float*)d_out;

    // Idempotent, capture-safe; no static guard.
    cudaFuncSetAttribute(rnn_persistent,
                         cudaFuncAttributeMaxDynamicSharedMemorySize,
                         (int)sizeof(Smem));

    rnn_persistent<<<NBLK, 256, sizeof(Smem)>>>(
        W_rec_m1, W_rec_pmd, W_rec_s1, W_pmd_m1, b_pmd_m1, W_m1_pmd,
        b_m1_pmd, W_s1_pmd, b_s1_pmd, W_in_s1, b_in_s1,
        W_out_m1, b_out_m1, W_fb_pmd, b_fb_pmd, stim, out);

    finale_kernel<<<T_STEPS, 128>>>(W_out_m1, b_out_m1, out);
}